// round 4
// baseline (speedup 1.0000x reference)
#include <cuda_runtime.h>
#include <stdint.h>

#define NSTEPS 2176
#define BURN   128
#define DD     512
#define HH     1024

// Scratch (static device globals — no allocation anywhere)
__device__ float g_sn[NSTEPS * DD];   // 0.1 * normal noise rows
__device__ float g_N [NSTEPS * HH];   // (0.1*noise_t) @ W1
__device__ float g_u [NSTEPS];        // uniform accept draws
__device__ uint2 g_knoise[NSTEPS];    // per-step noise subkeys

// ---------------- threefry2x32 (exact JAX) ----------------
__device__ __forceinline__ uint32_t rotl32(uint32_t v, int r) {
    return (v << r) | (v >> (32 - r));
}

__device__ __forceinline__ void threefry(uint32_t k0, uint32_t k1,
                                         uint32_t x0, uint32_t x1,
                                         uint32_t& o0, uint32_t& o1) {
    uint32_t ks2 = k0 ^ k1 ^ 0x1BD11BDAu;
    x0 += k0; x1 += k1;
#define TF_R(r) { x0 += x1; x1 = rotl32(x1, (r)); x1 ^= x0; }
    TF_R(13) TF_R(15) TF_R(26) TF_R(6)
    x0 += k1;  x1 += ks2 + 1u;
    TF_R(17) TF_R(29) TF_R(16) TF_R(24)
    x0 += ks2; x1 += k0 + 2u;
    TF_R(13) TF_R(15) TF_R(26) TF_R(6)
    x0 += k0;  x1 += k1 + 3u;
    TF_R(17) TF_R(29) TF_R(16) TF_R(24)
    x0 += k1;  x1 += ks2 + 4u;
    TF_R(13) TF_R(15) TF_R(26) TF_R(6)
    x0 += ks2; x1 += k0 + 5u;
#undef TF_R
    o0 = x0; o1 = x1;
}

// ---------------- XLA-matching math ----------------
// XLA ErfInv32 (Giles polynomial)
__device__ __forceinline__ float erfinv_xla(float x) {
    float w = -log1pf(-x * x);
    float p;
    if (w < 5.0f) {
        w = w - 2.5f;
        p = 2.81022636e-08f;
        p = fmaf(p, w, 3.43273939e-07f);
        p = fmaf(p, w, -3.5233877e-06f);
        p = fmaf(p, w, -4.39150654e-06f);
        p = fmaf(p, w, 0.00021858087f);
        p = fmaf(p, w, -0.00125372503f);
        p = fmaf(p, w, -0.00417768164f);
        p = fmaf(p, w, 0.246640727f);
        p = fmaf(p, w, 1.50140941f);
    } else {
        w = sqrtf(w) - 3.0f;
        p = -0.000200214257f;
        p = fmaf(p, w, 0.000100950558f);
        p = fmaf(p, w, 0.00134934322f);
        p = fmaf(p, w, -0.00367342844f);
        p = fmaf(p, w, 0.00573950773f);
        p = fmaf(p, w, -0.0076224613f);
        p = fmaf(p, w, 0.00943887047f);
        p = fmaf(p, w, 1.00167406f);
        p = fmaf(p, w, 2.83297682f);
    }
    return p * x;
}

// XLA EmitTanh f32 (Eigen rational approximation)
__device__ __forceinline__ float tanh_xla(float x) {
    const float kMax = 7.90531110763549805f;
    float xc = fminf(fmaxf(x, -kMax), kMax);
    float x2 = xc * xc;
    float np_ = fmaf(x2, -2.76076847742355e-16f, 2.00018790482477e-13f);
    np_ = fmaf(x2, np_, -8.60467152213735e-11f);
    np_ = fmaf(x2, np_, 5.12229709037114e-08f);
    np_ = fmaf(x2, np_, 1.48572235717979e-05f);
    np_ = fmaf(x2, np_, 6.37261928875436e-04f);
    np_ = fmaf(x2, np_, 4.89352455891786e-03f);
    np_ = xc * np_;
    float dp = fmaf(x2, 1.19825839466702e-06f, 1.18534705686654e-04f);
    dp = fmaf(x2, dp, 2.26843463243900e-03f);
    dp = fmaf(x2, dp, 4.89352518554385e-03f);
    float r = np_ / dp;
    return (fabsf(x) < 0.0004f) ? x : r;
}

__device__ __forceinline__ float bits_to_u01(uint32_t bits) {
    return __uint_as_float((bits >> 9) | 0x3F800000u) - 1.0f;
}

// jax.random.normal: u = uniform(key, lo=nextafter(-1,0), hi=1); sqrt(2)*erfinv(u)
// (hi - lo) rounds to exactly 2.0f in fp32; f*2 is exact, so mul+add == fma.
__device__ __forceinline__ float bits_to_scaled_normal(uint32_t bits) {
    const float lo = -0.99999994039535522461f;
    float f = bits_to_u01(bits);
    float v = fmaxf(lo, fmaf(f, 2.0f, lo));
    float n = 1.41421353816986083984f * erfinv_xla(v);
    return 0.1f * n;  // STEP_SIZE pre-applied
}

// ---------------- Phase 0: step keys + uniforms ----------------
// PARTITIONABLE threefry (jax_threefry_partitionable=True, default in modern JAX):
//  split(key, n) fold-like: key_t = both lanes of tf(key, hi=0, lo=t)
//  random_bits 32-bit: per-element counter (hi=0, lo=i), bits = lane0 ^ lane1
__global__ void keygen_kernel() {
    int t = blockIdx.x * blockDim.x + threadIdx.x;
    if (t >= NSTEPS) return;
    uint32_t a, b;
    threefry(0u, 1u, 0u, (uint32_t)t, a, b);      // keys = split(key(1), NSTEPS)
    uint32_t n0, n1, u0, u1;
    threefry(a, b, 0u, 0u, n0, n1);               // k_noise = split(key_t)[0]
    threefry(a, b, 0u, 1u, u0, u1);               // k_unif  = split(key_t)[1]
    g_knoise[t] = make_uint2(n0, n1);
    uint32_t c, d;
    threefry(u0, u1, 0u, 0u, c, d);               // uniform bits, shape (1,)
    g_u[t] = bits_to_u01(c ^ d);
}

// ---------------- Phase 1: scaled normals ----------------
// bits[i] = lane0 ^ lane1 of tf(k_noise, 0, i), i = 0..511
__global__ void noise_kernel() {
    int t = blockIdx.x;
    int i = threadIdx.x;  // 0..511
    uint2 k = g_knoise[t];
    uint32_t r0, r1;
    threefry(k.x, k.y, 0u, (uint32_t)i, r0, r1);
    g_sn[t * DD + i] = bits_to_scaled_normal(r0 ^ r1);
}

// ---------------- Phase 2: N = sn @ W1  (fp32, plain FFMA GEMM) ----------------
#define BM 64
#define BN 64
#define BK 16
__global__ __launch_bounds__(256) void gemm_kernel(const float* __restrict__ W1) {
    __shared__ float As[BK][BM];
    __shared__ float Bs[BK][BN];
    int m0 = blockIdx.y * BM;
    int n0 = blockIdx.x * BN;
    int tid = threadIdx.x;
    int tx = tid % 16, ty = tid / 16;
    float acc[4][4] = {};
    for (int k0 = 0; k0 < DD; k0 += BK) {
#pragma unroll
        for (int l = tid; l < BM * BK; l += 256) {
            int m = l / BK, k = l % BK;
            As[k][m] = g_sn[(m0 + m) * DD + k0 + k];
        }
#pragma unroll
        for (int l = tid; l < BK * BN; l += 256) {
            int k = l / BN, n = l % BN;
            Bs[k][n] = W1[(k0 + k) * HH + n0 + n];
        }
        __syncthreads();
#pragma unroll
        for (int kk = 0; kk < BK; kk++) {
            float a[4], b[4];
#pragma unroll
            for (int i = 0; i < 4; i++) a[i] = As[kk][ty * 4 + i];
#pragma unroll
            for (int j = 0; j < 4; j++) b[j] = Bs[kk][tx * 4 + j];
#pragma unroll
            for (int i = 0; i < 4; i++)
#pragma unroll
                for (int j = 0; j < 4; j++)
                    acc[i][j] = fmaf(a[i], b[j], acc[i][j]);
        }
        __syncthreads();
    }
#pragma unroll
    for (int i = 0; i < 4; i++)
#pragma unroll
        for (int j = 0; j < 4; j++)
            g_N[(m0 + ty * 4 + i) * HH + n0 + tx * 4 + j] = acc[i][j];
}

// ---------------- Phase 3: sequential MH chain (one persistent CTA) ----------------
__global__ __launch_bounds__(1024, 1) void chain_kernel(
    const float* __restrict__ x0, const float* __restrict__ W1,
    const float* __restrict__ b1, const float* __restrict__ W2,
    const float* __restrict__ b2, float* __restrict__ out) {
    int tid  = threadIdx.x;
    int lane = tid & 31;
    int w    = tid >> 5;

    __shared__ float s_x0[DD];
    __shared__ float s_part[32];
    __shared__ float s_acc;

    if (tid < DD) s_x0[tid] = x0[tid];
    __syncthreads();

    // z0_j = x0 @ W1[:, j]
    float z = 0.f;
#pragma unroll 8
    for (int d = 0; d < DD; d++) z = fmaf(s_x0[d], W1[d * HH + tid], z);

    float b1j = b1[tid];
    float w2j = W2[tid];
    float b2v = b2[0];
    float xj = (tid < DD) ? s_x0[tid] : 0.f;

    // initial p_old = psi2(x0), same reduction path as the loop
    {
        float h = tanh_xla(z + b1j);
        float p = h * w2j;
#pragma unroll
        for (int o = 16; o; o >>= 1) p += __shfl_xor_sync(0xFFFFFFFFu, p, o);
        if (lane == 0) s_part[w] = p;
        __syncthreads();
        if (w == 0) {
            float v = s_part[lane];
#pragma unroll
            for (int o = 16; o; o >>= 1) v += __shfl_xor_sync(0xFFFFFFFFu, v, o);
            if (lane == 0) s_acc = v;
        }
        __syncthreads();
    }
    float p_old = 0.f;
    if (tid == 0) {
        float o0 = s_acc + b2v;
        p_old = o0 * o0;
    }
    __syncthreads();

    // prefetch rows 0 and 1 (decision-independent)
    float Ncur  = g_N[tid];
    float Nnext = g_N[HH + tid];
    float sncur = 0.f, snnext = 0.f;
    if (tid < DD) { sncur = g_sn[tid]; snnext = g_sn[DD + tid]; }
    float ucur = 0.f, unext = 0.f;
    if (tid == 0) { ucur = g_u[0]; unext = g_u[1]; }

    for (int t = 0; t < NSTEPS; t++) {
        float pre = z + Ncur;                  // candidate z_new
        float h   = tanh_xla(pre + b1j);
        float p   = h * w2j;
#pragma unroll
        for (int o = 16; o; o >>= 1) p += __shfl_xor_sync(0xFFFFFFFFu, p, o);
        if (lane == 0) s_part[w] = p;
        __syncthreads();                       // A
        if (w == 0) {
            float v = s_part[lane];
#pragma unroll
            for (int o = 16; o; o >>= 1) v += __shfl_xor_sync(0xFFFFFFFFu, v, o);
            if (lane == 0) {
                float o_new  = v + b2v;
                float p_new  = o_new * o_new;
                float ratio  = fminf(p_new / (p_old + 1e-12f), 1.0f);
                bool  acc    = (ucur < ratio);
                if (acc) p_old = p_new;
                s_acc = acc ? 1.f : 0.f;
                ucur = unext;
                if (t + 2 < NSTEPS) unext = g_u[t + 2];
            }
        }
        __syncthreads();                       // B
        bool acc = (s_acc != 0.f);
        if (acc) z = pre;
        if (tid < DD) {
            if (acc) xj += sncur;
            if (t >= BURN) out[(t - BURN) * DD + tid] = xj;
            sncur = snnext;
            if (t + 2 < NSTEPS) snnext = g_sn[(t + 2) * DD + tid];
        }
        Ncur = Nnext;
        if (t + 2 < NSTEPS) Nnext = g_N[(t + 2) * HH + tid];
    }
}

// ---------------- launch ----------------
extern "C" void kernel_launch(void* const* d_in, const int* in_sizes, int n_in,
                              void* d_out, int out_size) {
    const float* x0 = (const float*)d_in[0];
    const float* W1 = (const float*)d_in[1];
    const float* b1 = (const float*)d_in[2];
    const float* W2 = (const float*)d_in[3];
    const float* b2 = (const float*)d_in[4];
    float* out = (float*)d_out;

    keygen_kernel<<<(NSTEPS + 255) / 256, 256>>>();
    noise_kernel<<<NSTEPS, 512>>>();
    gemm_kernel<<<dim3(HH / BN, NSTEPS / BM), 256>>>(W1);
    chain_kernel<<<1, 1024>>>(x0, W1, b1, W2, b2, out);
}

// round 5
// speedup vs baseline: 1.5608x; 1.5608x over previous
#include <cuda_runtime.h>
#include <stdint.h>

#define NSTEPS 2176
#define BURN   128
#define DD     512
#define HH     1024

// Scratch (static device globals — no allocation anywhere)
__device__ float g_sn[NSTEPS * DD];   // 0.1 * normal noise rows
__device__ float g_N [NSTEPS * HH];   // (0.1*noise_t) @ W1
__device__ float g_u [NSTEPS];        // uniform accept draws
__device__ uint2 g_knoise[NSTEPS];    // per-step noise subkeys

// ---------------- threefry2x32 (exact JAX) ----------------
__device__ __forceinline__ uint32_t rotl32(uint32_t v, int r) {
    return (v << r) | (v >> (32 - r));
}

__device__ __forceinline__ void threefry(uint32_t k0, uint32_t k1,
                                         uint32_t x0, uint32_t x1,
                                         uint32_t& o0, uint32_t& o1) {
    uint32_t ks2 = k0 ^ k1 ^ 0x1BD11BDAu;
    x0 += k0; x1 += k1;
#define TF_R(r) { x0 += x1; x1 = rotl32(x1, (r)); x1 ^= x0; }
    TF_R(13) TF_R(15) TF_R(26) TF_R(6)
    x0 += k1;  x1 += ks2 + 1u;
    TF_R(17) TF_R(29) TF_R(16) TF_R(24)
    x0 += ks2; x1 += k0 + 2u;
    TF_R(13) TF_R(15) TF_R(26) TF_R(6)
    x0 += k0;  x1 += k1 + 3u;
    TF_R(17) TF_R(29) TF_R(16) TF_R(24)
    x0 += k1;  x1 += ks2 + 4u;
    TF_R(13) TF_R(15) TF_R(26) TF_R(6)
    x0 += ks2; x1 += k0 + 5u;
#undef TF_R
    o0 = x0; o1 = x1;
}

// ---------------- XLA-matching math ----------------
// XLA ErfInv32 (Giles polynomial)
__device__ __forceinline__ float erfinv_xla(float x) {
    float w = -log1pf(-x * x);
    float p;
    if (w < 5.0f) {
        w = w - 2.5f;
        p = 2.81022636e-08f;
        p = fmaf(p, w, 3.43273939e-07f);
        p = fmaf(p, w, -3.5233877e-06f);
        p = fmaf(p, w, -4.39150654e-06f);
        p = fmaf(p, w, 0.00021858087f);
        p = fmaf(p, w, -0.00125372503f);
        p = fmaf(p, w, -0.00417768164f);
        p = fmaf(p, w, 0.246640727f);
        p = fmaf(p, w, 1.50140941f);
    } else {
        w = sqrtf(w) - 3.0f;
        p = -0.000200214257f;
        p = fmaf(p, w, 0.000100950558f);
        p = fmaf(p, w, 0.00134934322f);
        p = fmaf(p, w, -0.00367342844f);
        p = fmaf(p, w, 0.00573950773f);
        p = fmaf(p, w, -0.0076224613f);
        p = fmaf(p, w, 0.00943887047f);
        p = fmaf(p, w, 1.00167406f);
        p = fmaf(p, w, 2.83297682f);
    }
    return p * x;
}

// XLA EmitTanh f32 (Eigen rational approximation)
__device__ __forceinline__ float tanh_xla(float x) {
    const float kMax = 7.90531110763549805f;
    float xc = fminf(fmaxf(x, -kMax), kMax);
    float x2 = xc * xc;
    float np_ = fmaf(x2, -2.76076847742355e-16f, 2.00018790482477e-13f);
    np_ = fmaf(x2, np_, -8.60467152213735e-11f);
    np_ = fmaf(x2, np_, 5.12229709037114e-08f);
    np_ = fmaf(x2, np_, 1.48572235717979e-05f);
    np_ = fmaf(x2, np_, 6.37261928875436e-04f);
    np_ = fmaf(x2, np_, 4.89352455891786e-03f);
    np_ = xc * np_;
    float dp = fmaf(x2, 1.19825839466702e-06f, 1.18534705686654e-04f);
    dp = fmaf(x2, dp, 2.26843463243900e-03f);
    dp = fmaf(x2, dp, 4.89352518554385e-03f);
    float r = np_ / dp;
    return (fabsf(x) < 0.0004f) ? x : r;
}

__device__ __forceinline__ float bits_to_u01(uint32_t bits) {
    return __uint_as_float((bits >> 9) | 0x3F800000u) - 1.0f;
}

// jax.random.normal with STEP_SIZE pre-applied
__device__ __forceinline__ float bits_to_scaled_normal(uint32_t bits) {
    const float lo = -0.99999994039535522461f;
    float f = bits_to_u01(bits);
    float v = fmaxf(lo, fmaf(f, 2.0f, lo));
    float n = 1.41421353816986083984f * erfinv_xla(v);
    return 0.1f * n;
}

// ---------------- Phase 0: step keys + uniforms (partitionable threefry) ----------------
__global__ void keygen_kernel() {
    int t = blockIdx.x * blockDim.x + threadIdx.x;
    if (t >= NSTEPS) return;
    uint32_t a, b;
    threefry(0u, 1u, 0u, (uint32_t)t, a, b);      // keys = split(key(1), NSTEPS)
    uint32_t n0, n1, u0, u1;
    threefry(a, b, 0u, 0u, n0, n1);               // k_noise
    threefry(a, b, 0u, 1u, u0, u1);               // k_unif
    g_knoise[t] = make_uint2(n0, n1);
    uint32_t c, d;
    threefry(u0, u1, 0u, 0u, c, d);               // uniform bits, shape (1,)
    g_u[t] = bits_to_u01(c ^ d);
}

// ---------------- Phase 1: scaled normals ----------------
__global__ void noise_kernel() {
    int t = blockIdx.x;
    int i = threadIdx.x;  // 0..511
    uint2 k = g_knoise[t];
    uint32_t r0, r1;
    threefry(k.x, k.y, 0u, (uint32_t)i, r0, r1);
    g_sn[t * DD + i] = bits_to_scaled_normal(r0 ^ r1);
}

// ---------------- Phase 2: N = sn @ W1  (fp32 FFMA GEMM, DRAM-bound, ~3us) ----------------
#define BM 64
#define BN 64
#define BK 16
__global__ __launch_bounds__(256) void gemm_kernel(const float* __restrict__ W1) {
    __shared__ float As[BK][BM];
    __shared__ float Bs[BK][BN];
    int m0 = blockIdx.y * BM;
    int n0 = blockIdx.x * BN;
    int tid = threadIdx.x;
    int tx = tid % 16, ty = tid / 16;
    float acc[4][4] = {};
    for (int k0 = 0; k0 < DD; k0 += BK) {
#pragma unroll
        for (int l = tid; l < BM * BK; l += 256) {
            int m = l / BK, k = l % BK;
            As[k][m] = g_sn[(m0 + m) * DD + k0 + k];
        }
#pragma unroll
        for (int l = tid; l < BK * BN; l += 256) {
            int k = l / BN, n = l % BN;
            Bs[k][n] = W1[(k0 + k) * HH + n0 + n];
        }
        __syncthreads();
#pragma unroll
        for (int kk = 0; kk < BK; kk++) {
            float a[4], b[4];
#pragma unroll
            for (int i = 0; i < 4; i++) a[i] = As[kk][ty * 4 + i];
#pragma unroll
            for (int j = 0; j < 4; j++) b[j] = Bs[kk][tx * 4 + j];
#pragma unroll
            for (int i = 0; i < 4; i++)
#pragma unroll
                for (int j = 0; j < 4; j++)
                    acc[i][j] = fmaf(a[i], b[j], acc[i][j]);
        }
        __syncthreads();
    }
#pragma unroll
    for (int i = 0; i < 4; i++)
#pragma unroll
        for (int j = 0; j < 4; j++)
            g_N[(m0 + ty * 4 + i) * HH + n0 + tx * 4 + j] = acc[i][j];
}

// ---------------- Phase 3: sequential MH chain ----------------
// 256 threads, 4 hidden units/thread (float4), 2 x-dims/thread (float2).
// One __syncthreads per step; double-buffered partials; every thread
// redundantly reduces 8 partials and computes the accept decision.
__global__ __launch_bounds__(256, 1) void chain_kernel(
    const float* __restrict__ x0, const float* __restrict__ W1,
    const float* __restrict__ b1, const float* __restrict__ W2,
    const float* __restrict__ b2, float* __restrict__ out) {
    int tid  = threadIdx.x;
    int lane = tid & 31;
    int w    = tid >> 5;

    __shared__ __align__(16) float s_part[2][8];
    __shared__ float s_x0[DD];
    __shared__ float s_u[NSTEPS];

    for (int i = tid; i < NSTEPS; i += 256) s_u[i] = g_u[i];
    {
        float2 t2 = ((const float2*)x0)[tid];
        s_x0[2 * tid] = t2.x; s_x0[2 * tid + 1] = t2.y;
    }
    __syncthreads();

    // z_j = b1_j + x0 @ W1[:, j]   (b1 folded into z permanently)
    float z[4];
    {
        float4 bv = ((const float4*)b1)[tid];
        z[0] = bv.x; z[1] = bv.y; z[2] = bv.z; z[3] = bv.w;
    }
    const float4* W1v = (const float4*)W1;
#pragma unroll 4
    for (int d = 0; d < DD; d++) {
        float xv = s_x0[d];
        float4 wv = W1v[d * (HH / 4) + tid];
        z[0] = fmaf(xv, wv.x, z[0]);
        z[1] = fmaf(xv, wv.y, z[1]);
        z[2] = fmaf(xv, wv.z, z[2]);
        z[3] = fmaf(xv, wv.w, z[3]);
    }

    float4 w2v = ((const float4*)W2)[tid];
    float b2v = b2[0];
    float2 x = ((const float2*)x0)[tid];

    // initial p_old = psi2(x0), same reduction structure as the loop (buffer 1)
    float p_old;
    {
        float h, p;
        h = tanh_xla(z[0]); p = h * w2v.x;
        h = tanh_xla(z[1]); p = fmaf(h, w2v.y, p);
        h = tanh_xla(z[2]); p = fmaf(h, w2v.z, p);
        h = tanh_xla(z[3]); p = fmaf(h, w2v.w, p);
#pragma unroll
        for (int o = 16; o; o >>= 1) p += __shfl_xor_sync(0xFFFFFFFFu, p, o);
        if (lane == 0) s_part[1][w] = p;
        __syncthreads();
        float4 pa = *(const float4*)&s_part[1][0];
        float4 pb = *(const float4*)&s_part[1][4];
        float v = ((pa.x + pa.y) + (pa.z + pa.w)) + ((pb.x + pb.y) + (pb.z + pb.w));
        float o_ = v + b2v;
        p_old = o_ * o_;
    }

    // prefetch (rows are decision-independent; depth 2, L2-resident)
    const float4* Nv  = (const float4*)g_N;   // row stride HH/4 = 256
    const float2* snv = (const float2*)g_sn;  // row stride DD/2 = 256
    float4 Nc  = Nv[tid];
    float4 Nn  = Nv[256 + tid];
    float2 sc  = snv[tid];
    float2 sn2 = snv[256 + tid];
    float  uc  = s_u[0];
    float  un  = s_u[1];

#pragma unroll 2
    for (int t = 0; t < NSTEPS; t++) {
        float pre0 = z[0] + Nc.x;
        float pre1 = z[1] + Nc.y;
        float pre2 = z[2] + Nc.z;
        float pre3 = z[3] + Nc.w;
        float h, p;
        h = tanh_xla(pre0); p = h * w2v.x;
        h = tanh_xla(pre1); p = fmaf(h, w2v.y, p);
        h = tanh_xla(pre2); p = fmaf(h, w2v.z, p);
        h = tanh_xla(pre3); p = fmaf(h, w2v.w, p);
#pragma unroll
        for (int o = 16; o; o >>= 1) p += __shfl_xor_sync(0xFFFFFFFFu, p, o);
        if (lane == 0) s_part[t & 1][w] = p;
        __syncthreads();                       // the only barrier per step

        float4 pa = *(const float4*)&s_part[t & 1][0];
        float4 pb = *(const float4*)&s_part[t & 1][4];
        float v = ((pa.x + pa.y) + (pa.z + pa.w)) + ((pb.x + pb.y) + (pb.z + pb.w));
        float o_    = v + b2v;
        float p_new = o_ * o_;
        float ratio = fminf(p_new / (p_old + 1e-12f), 1.0f);
        bool  acc   = (uc < ratio);
        if (acc) {
            p_old = p_new;
            z[0] = pre0; z[1] = pre1; z[2] = pre2; z[3] = pre3;
            x.x += sc.x; x.y += sc.y;
        }
        if (t >= BURN) ((float2*)out)[(t - BURN) * (DD / 2) + tid] = x;

        Nc = Nn; sc = sn2; uc = un;
        if (t + 2 < NSTEPS) {
            Nn  = Nv[(t + 2) * 256 + tid];
            sn2 = snv[(t + 2) * 256 + tid];
            un  = s_u[t + 2];
        }
    }
}

// ---------------- launch ----------------
extern "C" void kernel_launch(void* const* d_in, const int* in_sizes, int n_in,
                              void* d_out, int out_size) {
    const float* x0 = (const float*)d_in[0];
    const float* W1 = (const float*)d_in[1];
    const float* b1 = (const float*)d_in[2];
    const float* W2 = (const float*)d_in[3];
    const float* b2 = (const float*)d_in[4];
    float* out = (float*)d_out;

    keygen_kernel<<<(NSTEPS + 255) / 256, 256>>>();
    noise_kernel<<<NSTEPS, 512>>>();
    gemm_kernel<<<dim3(HH / BN, NSTEPS / BM), 256>>>(W1);
    chain_kernel<<<1, 256>>>(x0, W1, b1, W2, b2, out);
}